// round 1
// baseline (speedup 1.0000x reference)
#include <cuda_runtime.h>
#include <math.h>

#define C    2048
#define GRID 148
#define NT   512

// ------------------------ persistent-kernel scratch (device globals; no allocs) ------------------------
__device__ __align__(16) float g_inp[C];          // normalized h3 of previous step (RNN input)
__device__ __align__(16) float g_hid[2][4][C];    // double-buffered normalized hidden states
__device__ __align__(16) float g_hraw[3][C];      // raw relu outputs h0..h2 within a step
__device__ __align__(16) float g_lp[2][C];        // LengthProducer hidden activations
__device__ unsigned g_bar;                        // global barrier counter (reset each launch)

// Near-exact compensated accumulation: TwoProd (FMA) + Kahan, all with round-to-nearest
// intrinsics so fast-math / FMA contraction cannot reassociate anything.
__device__ __forceinline__ void kacc(float a, float b, float& s, float& cmp, float& es) {
    float p = __fmul_rn(a, b);
    float e = __fmaf_rn(a, b, -p);      // exact low part of the product
    float y = __fsub_rn(p, cmp);
    float t = __fadd_rn(s, y);
    cmp = __fsub_rn(__fsub_rn(t, s), y);
    s = t;
    es = __fadd_rn(es, e);
}

// Warp-collective 2048-length dot product: lane handles 16 float4 chunks (stride-32),
// compensated per-lane sum, fp64 cross-lane shuffle reduction. Result valid on lane 0,
// correctly rounded to fp32 (error ~1e-13 abs vs exact real arithmetic).
__device__ __forceinline__ float dotC(const float* __restrict__ wrow,
                                      const float* __restrict__ v, int lane) {
    float s = 0.f, cmp = 0.f, es = 0.f;
    const float4* w4 = reinterpret_cast<const float4*>(wrow);
    const float4* v4 = reinterpret_cast<const float4*>(v);
#pragma unroll
    for (int i = 0; i < 16; i++) {
        int idx = lane + 32 * i;
        float4 a = w4[idx];
        float4 b = v4[idx];
        kacc(a.x, b.x, s, cmp, es);
        kacc(a.y, b.y, s, cmp, es);
        kacc(a.z, b.z, s, cmp, es);
        kacc(a.w, b.w, s, cmp, es);
    }
    double d = (double)s + (double)cmp + (double)es;
#pragma unroll
    for (int o = 16; o > 0; o >>= 1)
        d += __shfl_down_sync(0xffffffffu, d, o);
    return (float)d;
}

// Grid-wide barrier: release (fence + relaxed atomic) / acquire (ld.acquire.gpu) poll.
// Monotonic counter; target = phase_index * GRID. All 148 CTAs are co-resident.
__device__ __forceinline__ void gbar(unsigned target) {
    __syncthreads();
    if (threadIdx.x == 0) {
        __threadfence();
        atomicAdd(&g_bar, 1u);
        unsigned v;
        do {
            asm volatile("ld.global.acquire.gpu.u32 %0, [%1];"
                         : "=r"(v) : "l"(&g_bar) : "memory");
        } while (v < target);
    }
    __syncthreads();
}

__global__ void rnn_init(const float* __restrict__ x) {
    int i = blockIdx.x * blockDim.x + threadIdx.x;
    if (i == 0) g_bar = 0u;
    if (i < C) {
        g_inp[i] = 0.f;                 // inp0 = zeros
        g_hid[0][0][i] = x[i];          // hid0[0] = x
        g_hid[0][1][i] = 0.f;
        g_hid[0][2][i] = 0.f;
        g_hid[0][3][i] = 0.f;
    }
}

__global__ void __launch_bounds__(NT, 1) rnn_main(
    const float* __restrict__ x,
    const float* __restrict__ lp_w,  const float* __restrict__ lp_b,
    const float* __restrict__ lp_wout, const float* __restrict__ lp_bout,
    const float* __restrict__ w_ih,  const float* __restrict__ b_ih,
    const float* __restrict__ w_hh,  const float* __restrict__ b_hh,
    float* __restrict__ out, int T, int has_l)
{
    __shared__ float s_a[C];
    __shared__ float s_b[C];
    const int tid  = threadIdx.x;
    const int w    = tid >> 5;
    const int lane = tid & 31;
    const int bid  = blockIdx.x;
    const int j    = w * GRID + bid;      // output row owned by this warp (j<2048 for ~14 warps/CTA)
    unsigned phase = 0;

    // ---------------- LengthProducer: 3 hidden Linear + LeakyReLU(0.2) ----------------
    for (int i = 0; i < 3; i++) {
        const float* vin = (i == 0) ? x : g_lp[(i - 1) & 1];
        reinterpret_cast<float4*>(s_a)[tid] = reinterpret_cast<const float4*>(vin)[tid];
        __syncthreads();
        if (j < C) {
            float d = dotC(lp_w + (size_t)i * C * C + (size_t)j * C, s_a, lane);
            if (lane == 0) {
                float z = __fadd_rn(d, lp_b[i * C + j]);
                g_lp[i & 1][j] = (z >= 0.f) ? z : __fmul_rn(0.2f, z);
            }
        }
        ++phase; gbar(phase * GRID);
    }
    // ---------------- LP output scalar: l = min(|y@wout + bout|, 0.9999) ----------------
    if (bid == 0 && w == 0) {
        float d = dotC(lp_wout, g_lp[0], lane);   // g_lp[0] holds layer-2 output
        if (lane == 0 && has_l > 0) {
            float z = __fadd_rn(d, lp_bout[0]);
            out[(size_t)T * C] = fminf(fabsf(z), 0.9999f);
        }
    }
    ++phase; gbar(phase * GRID);

    // ---------------- 4-layer ReLU RNN scan, T steps ----------------
    for (int t = 0; t < T; t++) {
        const int p = t & 1;
        for (int l = 0; l < 4; l++) {
            const float* vin = (l == 0) ? g_inp : g_hraw[l - 1];
            reinterpret_cast<float4*>(s_a)[tid] = reinterpret_cast<const float4*>(vin)[tid];
            reinterpret_cast<float4*>(s_b)[tid] = reinterpret_cast<const float4*>(g_hid[p][l])[tid];
            __syncthreads();
            if (j < C) {
                float dih = dotC(w_ih + (size_t)l * C * C + (size_t)j * C, s_a, lane);
                float dhh = dotC(w_hh + (size_t)l * C * C + (size_t)j * C, s_b, lane);
                if (lane == 0) {
                    // replicate ref rounding: ((dih + b_ih) + dhh) + b_hh, all fp32 RN
                    float pre = __fadd_rn(__fadd_rn(__fadd_rn(dih, b_ih[l * C + j]), dhh),
                                          b_hh[l * C + j]);
                    float h = fmaxf(pre, 0.f);
                    // _unit_norm over a size-1 axis: n = sqrt(h*h); h / (n + 1e-12)
                    float n  = __fsqrt_rn(__fmul_rn(h, h));
                    float hn = __fdiv_rn(h, __fadd_rn(n, 1e-12f));
                    g_hid[p ^ 1][l][j] = hn;
                    if (l < 3) {
                        g_hraw[l][j] = h;
                    } else {
                        g_inp[j] = hn;
                        out[(size_t)t * C + j] = hn;   // seq[t] = normalized h3
                    }
                }
            }
            ++phase; gbar(phase * GRID);
        }
    }
}

extern "C" void kernel_launch(void* const* d_in, const int* in_sizes, int n_in,
                              void* d_out, int out_size) {
    const float* x       = (const float*)d_in[0];
    const float* lp_w    = (const float*)d_in[1];
    const float* lp_b    = (const float*)d_in[2];
    const float* lp_wout = (const float*)d_in[3];
    const float* lp_bout = (const float*)d_in[4];
    const float* w_ih    = (const float*)d_in[5];
    const float* b_ih    = (const float*)d_in[6];
    const float* w_hh    = (const float*)d_in[7];
    const float* b_hh    = (const float*)d_in[8];
    float* out = (float*)d_out;

    int T     = out_size / C;        // 512 seq rows
    int has_l = out_size - T * C;    // trailing scalar l present?

    rnn_init<<<8, 256>>>(x);
    rnn_main<<<GRID, NT>>>(x, lp_w, lp_b, lp_wout, lp_bout,
                           w_ih, b_ih, w_hh, b_hh, out, T, has_l);
}

// round 3
// speedup vs baseline: 1.1594x; 1.1594x over previous
#include <cuda_runtime.h>
#include <math.h>

#define C    2048
#define GRID 148
#define NT   512

// ---------------- persistent-kernel scratch (device globals; no allocs) ----------------
__device__ __align__(16) float g_inp[C];          // normalized h3 of previous step (RNN input)
__device__ __align__(16) float g_hid[2][4][C];    // double-buffered normalized hidden states
__device__ __align__(16) float g_hraw[3][C];      // raw relu outputs h0..h2 within a step
__device__ __align__(16) float g_lp[2][C];        // LengthProducer hidden activations
__device__ unsigned g_bar;                        // global barrier counter (reset each launch)

// Near-exact compensated accumulation: TwoProd (FMA) + Kahan, all round-to-nearest intrinsics.
__device__ __forceinline__ void kacc(float a, float b, float& s, float& cmp, float& es) {
    float p = __fmul_rn(a, b);
    float e = __fmaf_rn(a, b, -p);
    float y = __fsub_rn(p, cmp);
    float t = __fadd_rn(s, y);
    cmp = __fsub_rn(__fsub_rn(t, s), y);
    s = t;
    es = __fadd_rn(es, e);
}
__device__ __forceinline__ void kacc4(float4 a, float4 b, float& s, float& c, float& e) {
    kacc(a.x, b.x, s, c, e); kacc(a.y, b.y, s, c, e);
    kacc(a.z, b.z, s, c, e); kacc(a.w, b.w, s, c, e);
}

// 256-bit (8-float) weight chunk. sm_103a requires v8.b32/v4.b64 width for L2 evict hints.
struct F8 { float4 lo, hi; };

__device__ __forceinline__ F8 unpack8(unsigned long long a, unsigned long long b,
                                      unsigned long long c, unsigned long long d) {
    F8 r;
    r.lo.x = __uint_as_float((unsigned)a); r.lo.y = __uint_as_float((unsigned)(a >> 32));
    r.lo.z = __uint_as_float((unsigned)b); r.lo.w = __uint_as_float((unsigned)(b >> 32));
    r.hi.x = __uint_as_float((unsigned)c); r.hi.y = __uint_as_float((unsigned)(c >> 32));
    r.hi.z = __uint_as_float((unsigned)d); r.hi.w = __uint_as_float((unsigned)(d >> 32));
    return r;
}

// POL=0: evict_last (pin ~96MB resident set in L2); POL=1: evict_first (stream 32MB).
template<int POL>
__device__ __forceinline__ F8 ldw8(const F8* p) {
    unsigned long long a, b, c, d;
    if (POL == 0)
        asm("ld.global.nc.L2::evict_last.v4.b64 {%0,%1,%2,%3}, [%4];"
            : "=l"(a), "=l"(b), "=l"(c), "=l"(d) : "l"(p));
    else
        asm("ld.global.nc.L2::evict_first.v4.b64 {%0,%1,%2,%3}, [%4];"
            : "=l"(a), "=l"(b), "=l"(c), "=l"(d) : "l"(p));
    return unpack8(a, b, c, d);
}
// Volatile variant: pinned in program order (issued before the barrier spin) for prefetch.
template<int POL>
__device__ __forceinline__ F8 ldw8v(const F8* p) {
    unsigned long long a, b, c, d;
    if (POL == 0)
        asm volatile("ld.global.nc.L2::evict_last.v4.b64 {%0,%1,%2,%3}, [%4];"
            : "=l"(a), "=l"(b), "=l"(c), "=l"(d) : "l"(p));
    else
        asm volatile("ld.global.nc.L2::evict_first.v4.b64 {%0,%1,%2,%3}, [%4];"
            : "=l"(a), "=l"(b), "=l"(c), "=l"(d) : "l"(p));
    return unpack8(a, b, c, d);
}

// Split grid barrier: arrive (release) / wait (acquire poll). All 148 CTAs co-resident.
__device__ __forceinline__ void gbar_arrive() {
    __syncthreads();
    if (threadIdx.x == 0) {
        __threadfence();
        atomicAdd(&g_bar, 1u);
    }
}
__device__ __forceinline__ void gbar_wait(unsigned target) {
    if (threadIdx.x == 0) {
        unsigned v;
        do {
            asm volatile("ld.global.acquire.gpu.u32 %0, [%1];"
                         : "=r"(v) : "l"(&g_bar) : "memory");
        } while (v < target);
    }
    __syncthreads();
}

__global__ void rnn_init(const float* __restrict__ x) {
    int i = blockIdx.x * blockDim.x + threadIdx.x;
    if (i == 0) g_bar = 0u;
    if (i < C) {
        g_inp[i] = 0.f;
        g_hid[0][0][i] = x[i];
        g_hid[0][1][i] = 0.f;
        g_hid[0][2][i] = 0.f;
        g_hid[0][3][i] = 0.f;
    }
}

// LengthProducer dot: plain 128-bit loads (one-shot traffic), Kahan + fp64 reduce.
__device__ __forceinline__ float dotLP(const float* __restrict__ wrow,
                                       const float* __restrict__ v, int lane) {
    float s = 0.f, c = 0.f, e = 0.f;
    const float4* w4 = reinterpret_cast<const float4*>(wrow);
    const float4* v4 = reinterpret_cast<const float4*>(v);
#pragma unroll
    for (int i = 0; i < 16; i++) {
        float4 a = __ldg(w4 + lane + 32 * i);
        float4 b = v4[lane + 32 * i];
        kacc4(a, b, s, c, e);
    }
    double d = (double)s + (double)c + (double)e;
#pragma unroll
    for (int o = 16; o > 0; o >>= 1)
        d += __shfl_down_sync(0xffffffffu, d, o);
    return (float)d;
}

// One RNN phase (layer l of step t). PIH/PHH: L2 policy of this phase's weights.
// NIH/NHH: policy of the NEXT phase's weights (chunk-0 prefetched across the barrier
// in A0,A1 / B0,B1). Row dot = 64 float8 slots; lane owns slots lane+32k, k=0..7,
// organized as 4 chunks of 2 slots, software-pipelined (load ch+1 while computing ch).
template<int PIH, int PHH, int NIH, int NHH>
__device__ __forceinline__ void rnn_phase(
    int l, int t, int p, int nl, int np,
    int j, int lane, int tid, unsigned& ph,
    const float* __restrict__ w_ih, const float* __restrict__ w_hh,
    const float* __restrict__ b_ih, const float* __restrict__ b_hh,
    float* __restrict__ out,
    float* s_a, float* s_b,
    F8& A0, F8& A1, F8& B0, F8& B1)
{
    gbar_wait(ph * GRID);                      // this phase's inputs are now published
    const float* vin = (l == 0) ? g_inp : g_hraw[l - 1];
    reinterpret_cast<float4*>(s_a)[tid] = reinterpret_cast<const float4*>(vin)[tid];
    __syncthreads();

    if (j < C) {
        const F8* wa8 = reinterpret_cast<const F8*>(w_ih + ((size_t)l * C + j) * C);
        const F8* wb8 = reinterpret_cast<const F8*>(w_hh + ((size_t)l * C + j) * C);
        const float4* a4 = reinterpret_cast<const float4*>(s_a);
        const float4* b4 = reinterpret_cast<const float4*>(s_b);
        float sa = 0.f, ca = 0.f, ea = 0.f, sb = 0.f, cb = 0.f, eb = 0.f;
        F8 x0 = A0, x1 = A1, y0 = B0, y1 = B1;
#pragma unroll
        for (int ch = 0; ch < 4; ch++) {
            F8 n0, n1, m0, m1;
            if (ch < 3) {                       // stream chunk ch+1 while computing chunk ch
                int o = lane + 64 * (ch + 1);
                n0 = ldw8<PIH>(wa8 + o); n1 = ldw8<PIH>(wa8 + o + 32);
                m0 = ldw8<PHH>(wb8 + o); m1 = ldw8<PHH>(wb8 + o + 32);
            }
            int e = lane + 64 * ch;             // float8 slot; float4 indices 2e, 2e+1
            kacc4(x0.lo, a4[2 * e],           sa, ca, ea);
            kacc4(x0.hi, a4[2 * e + 1],       sa, ca, ea);
            kacc4(x1.lo, a4[2 * (e + 32)],    sa, ca, ea);
            kacc4(x1.hi, a4[2 * (e + 32) + 1],sa, ca, ea);
            kacc4(y0.lo, b4[2 * e],           sb, cb, eb);
            kacc4(y0.hi, b4[2 * e + 1],       sb, cb, eb);
            kacc4(y1.lo, b4[2 * (e + 32)],    sb, cb, eb);
            kacc4(y1.hi, b4[2 * (e + 32) + 1],sb, cb, eb);
            if (ch < 3) { x0 = n0; x1 = n1; y0 = m0; y1 = m1; }
        }
        double da = (double)sa + (double)ca + (double)ea;
        double db = (double)sb + (double)cb + (double)eb;
#pragma unroll
        for (int o = 16; o > 0; o >>= 1) {
            da += __shfl_down_sync(0xffffffffu, da, o);
            db += __shfl_down_sync(0xffffffffu, db, o);
        }
        if (lane == 0) {
            // ref rounding: ((dih + b_ih) + dhh) + b_hh, all fp32 RN
            float pre = __fadd_rn(__fadd_rn(__fadd_rn((float)da, b_ih[l * C + j]),
                                            (float)db), b_hh[l * C + j]);
            float h  = fmaxf(pre, 0.f);
            float n  = __fsqrt_rn(__fmul_rn(h, h));
            float hn = __fdiv_rn(h, __fadd_rn(n, 1e-12f));
            g_hid[p ^ 1][l][j] = hn;
            if (l < 3) g_hraw[l][j] = h;
            else { g_inp[j] = hn; out[(size_t)t * C + j] = hn; }
        }
    }

    // ---- tail: prefetch next phase's chunk 0 (overlaps barrier round-trip), arrive, stage s_b ----
    if (j < C) {
        const F8* na = reinterpret_cast<const F8*>(w_ih + ((size_t)nl * C + j) * C);
        const F8* nb = reinterpret_cast<const F8*>(w_hh + ((size_t)nl * C + j) * C);
        A0 = ldw8v<NIH>(na + lane); A1 = ldw8v<NIH>(na + lane + 32);
        B0 = ldw8v<NHH>(nb + lane); B1 = ldw8v<NHH>(nb + lane + 32);
    }
    gbar_arrive();
    // next phase's hid operand has been stable for >=3 barriers: stage pre-wait
    reinterpret_cast<float4*>(s_b)[tid] =
        reinterpret_cast<const float4*>(g_hid[np][nl])[tid];
    ++ph;
}

__global__ void __launch_bounds__(NT, 1) rnn_main(
    const float* __restrict__ x,
    const float* __restrict__ lp_w,  const float* __restrict__ lp_b,
    const float* __restrict__ lp_wout, const float* __restrict__ lp_bout,
    const float* __restrict__ w_ih,  const float* __restrict__ b_ih,
    const float* __restrict__ w_hh,  const float* __restrict__ b_hh,
    float* __restrict__ out, int T, int has_l)
{
    __shared__ float s_a[C];
    __shared__ float s_b[C];
    const int tid  = threadIdx.x;
    const int w    = tid >> 5;
    const int lane = tid & 31;
    const int bid  = blockIdx.x;
    const int j    = w * GRID + bid;
    unsigned ph = 0;

    // ---------------- LengthProducer: 3 hidden Linear + LeakyReLU(0.2) ----------------
    for (int i = 0; i < 3; i++) {
        const float* vin = (i == 0) ? x : g_lp[(i - 1) & 1];
        reinterpret_cast<float4*>(s_a)[tid] = reinterpret_cast<const float4*>(vin)[tid];
        __syncthreads();
        if (j < C) {
            float d = dotLP(lp_w + (size_t)i * C * C + (size_t)j * C, s_a, lane);
            if (lane == 0) {
                float z = __fadd_rn(d, lp_b[i * C + j]);
                g_lp[i & 1][j] = (z >= 0.f) ? z : __fmul_rn(0.2f, z);
            }
        }
        gbar_arrive(); ++ph; gbar_wait(ph * GRID);
    }
    // ---------------- LP output scalar: l = min(|y@wout + bout|, 0.9999) ----------------
    if (bid == 0 && w == 0) {
        float d = dotLP(lp_wout, g_lp[0], lane);
        if (lane == 0 && has_l > 0) {
            float z = __fadd_rn(d, lp_bout[0]);
            out[(size_t)T * C] = fminf(fabsf(z), 0.9999f);
        }
    }
    // prefetch RNN phase (t=0, l=0) chunk 0 and stage its hid operand before arriving
    F8 A0, A1, B0, B1;
    if (j < C) {
        const F8* na = reinterpret_cast<const F8*>(w_ih + (size_t)j * C);
        const F8* nb = reinterpret_cast<const F8*>(w_hh + (size_t)j * C);
        A0 = ldw8v<0>(na + lane); A1 = ldw8v<0>(na + lane + 32);
        B0 = ldw8v<0>(nb + lane); B1 = ldw8v<0>(nb + lane + 32);
    }
    gbar_arrive();
    reinterpret_cast<float4*>(s_b)[tid] = reinterpret_cast<const float4*>(g_hid[0][0])[tid];
    ++ph;

    // ---------------- 4-layer ReLU RNN scan, T steps ----------------
    // L2 policy map: w_ih all layers pinned (64MB) + w_hh layers 0-1 pinned (32MB) = 96MB
    // evict_last resident set; w_hh layers 2-3 (32MB) streamed evict_first.
    for (int t = 0; t < T; t++) {
        const int p = t & 1;
        rnn_phase<0,0, 0,0>(0, t, p, 1, p,     j, lane, tid, ph, w_ih, w_hh, b_ih, b_hh,
                            out, s_a, s_b, A0, A1, B0, B1);
        rnn_phase<0,0, 0,1>(1, t, p, 2, p,     j, lane, tid, ph, w_ih, w_hh, b_ih, b_hh,
                            out, s_a, s_b, A0, A1, B0, B1);
        rnn_phase<0,1, 0,1>(2, t, p, 3, p,     j, lane, tid, ph, w_ih, w_hh, b_ih, b_hh,
                            out, s_a, s_b, A0, A1, B0, B1);
        rnn_phase<0,1, 0,0>(3, t, p, 0, p ^ 1, j, lane, tid, ph, w_ih, w_hh, b_ih, b_hh,
                            out, s_a, s_b, A0, A1, B0, B1);
    }
}

extern "C" void kernel_launch(void* const* d_in, const int* in_sizes, int n_in,
                              void* d_out, int out_size) {
    const float* x       = (const float*)d_in[0];
    const float* lp_w    = (const float*)d_in[1];
    const float* lp_b    = (const float*)d_in[2];
    const float* lp_wout = (const float*)d_in[3];
    const float* lp_bout = (const float*)d_in[4];
    const float* w_ih    = (const float*)d_in[5];
    const float* b_ih    = (const float*)d_in[6];
    const float* w_hh    = (const float*)d_in[7];
    const float* b_hh    = (const float*)d_in[8];
    float* out = (float*)d_out;

    int T     = out_size / C;        // 512 seq rows
    int has_l = out_size - T * C;    // trailing scalar l present?

    rnn_init<<<8, 256>>>(x);
    rnn_main<<<GRID, NT>>>(x, lp_w, lp_b, lp_wout, lp_bout,
                           w_ih, b_ih, w_hh, b_hh, out, T, has_l);
}